// round 16
// baseline (speedup 1.0000x reference)
#include <cuda_runtime.h>
#include <cuda_bf16.h>

// out[b,s,e] = W_e[e, tokens[b,s]] + W_p[s,e]
// tokens: (2,2048) int32, W_e: (1024,32000) f32, W_p: (2048,1024) f32
// out: (2,2048,1024) f32
//
// Streaming v10: deep DMA pipeline.
// R15 (bulk-copy, double buffer) is DRAM-bound at 5.36TB/s = in-flight-bytes
// limited: 6 blocks/SM x 1 outstanding 16KB tile = 96KB/SM in flight. v10:
// ET=8 with a 4-buffer ring (same 33.3KB smem -> still 6 blocks/SM) and
// prefetch depth 3 => 144KB/SM in flight (+50%). Keeps the single-wave
// schedule (125 bins x 7 = 875 blocks), once-per-block bin scan, bulk
// row-copies completing on per-buffer mbarriers.

#define B 2
#define S 2048
#define E 1024
#define V 32000
#define NTOK (B * S)       // 4096

#define V_TILE 256
#define NBINS (V / V_TILE) // 125
#define ET 8               // e-rows per subtile (8KB tiles)
#define NBUF 4             // buffer ring; prefetch depth 3
#define KPB 7              // blocks per bin -> grid 875 (single wave @ 6/SM)
#define SSTRIDE 260        // rows 1040B apart; 16B-aligned bulk dst
#define CAP 512            // hit-list capacity (bin avg ~33; fallback if over)
#define TILE_BYTES (ET * V_TILE * 4)   // 8192

__global__ __launch_bounds__(256, 6)
void embed_kernel(const int* __restrict__ tokens,
                  const float* __restrict__ W_e,
                  const float* __restrict__ W_p,
                  float* __restrict__ out) {
    __shared__ int   list[CAP];                               // 2KB
    __shared__ __align__(16) float tile[NBUF][ET * SSTRIDE];  // 33.3KB
    __shared__ __align__(8) unsigned long long mbar[NBUF];
    __shared__ int   s_cnt;

    int bin = blockIdx.x % NBINS;
    int k   = blockIdx.x / NBINS;               // 0..6
    // 128 ET=8 tiles per bin, split 19+19+18*5 across 7 blocks.
    int nt  = (k < 2) ? 19 : 18;
    int t0  = (k < 2) ? 19 * k : 38 + 18 * (k - 2);
    int v0  = bin << 8;
    int tid = threadIdx.x;

    unsigned mb[NBUF];
#pragma unroll
    for (int b = 0; b < NBUF; b++)
        mb[b] = (unsigned)__cvta_generic_to_shared(&mbar[b]);

    if (tid == 0) {
        s_cnt = 0;
#pragma unroll
        for (int b = 0; b < NBUF; b++)
            asm volatile("mbarrier.init.shared.b64 [%0], 1;" :: "r"(mb[b]));
        asm volatile("fence.proxy.async.shared::cta;" ::: "memory");
    }
    __syncthreads();                            // init + s_cnt visible

    // ---- Prologue: issue up to 3 tiles (8 bulk 1KB row-copies each).
    if (tid == 0) {
#pragma unroll
        for (int t = 0; t < 3; t++) {
            if (t < nt) {
                asm volatile("mbarrier.arrive.expect_tx.shared.b64 _, [%0], %1;"
                             :: "r"(mb[t]), "r"(TILE_BYTES));
#pragma unroll
                for (int r = 0; r < ET; r++) {
                    const float* src = W_e + (size_t)((t0 + t) * ET + r) * V + v0;
                    unsigned dst = (unsigned)__cvta_generic_to_shared(
                        &tile[t][r * SSTRIDE]);
                    asm volatile(
                        "cp.async.bulk.shared::cta.global.mbarrier::complete_tx::bytes"
                        " [%0], [%1], %2, [%3];"
                        :: "r"(dst), "l"(src), "r"(V_TILE * 4), "r"(mb[t]) : "memory");
                }
            }
        }
    }

    // ---- Scan: compact this bin's tokens (hidden under the first fetches).
#pragma unroll
    for (int i = 0; i < 4; i++) {
        int4 tv = __ldg(reinterpret_cast<const int4*>(tokens) + tid + 256 * i);
        int tk0 = (tid + 256 * i) * 4;
        int vv[4] = {tv.x, tv.y, tv.z, tv.w};
#pragma unroll
        for (int kk = 0; kk < 4; kk++) {
            if ((vv[kk] >> 8) == bin) {
                int pos = atomicAdd(&s_cnt, 1);
                if (pos < CAP) list[pos] = ((tk0 + kk) << 8) | (vv[kk] & 255);
            }
        }
    }
    __syncthreads();
    int total = s_cnt;

    if (total <= CAP) {
        int j  = tid & 1;                       // float4 slot (8 floats/row)
        int hb = tid >> 1;                      // 128 tokens per pass
        for (int t = 0; t < nt; t++) {
            // Issue tile t+3 into buffer (t+3)&3 (= (t-1)&3, drained before
            // the previous iteration's closing __syncthreads).
            if (t + 3 < nt && tid == 0) {
                int bidx = (t + 3) & 3;
                asm volatile("mbarrier.arrive.expect_tx.shared.b64 _, [%0], %1;"
                             :: "r"(mb[bidx]), "r"(TILE_BYTES));
#pragma unroll
                for (int r = 0; r < ET; r++) {
                    const float* src = W_e + (size_t)((t0 + t + 3) * ET + r) * V + v0;
                    unsigned dst = (unsigned)__cvta_generic_to_shared(
                        &tile[bidx][r * SSTRIDE]);
                    asm volatile(
                        "cp.async.bulk.shared::cta.global.mbarrier::complete_tx::bytes"
                        " [%0], [%1], %2, [%3];"
                        :: "r"(dst), "l"(src), "r"(V_TILE * 4), "r"(mb[bidx]) : "memory");
                }
            }

            // Wait tile t: buffer t&3, phase (t>>2)&1 (HW-sleep try_wait).
            {
                unsigned mbw = mb[t & 3];
                unsigned ph  = (t >> 2) & 1;
                unsigned done;
                asm volatile(
                    "{\n\t.reg .pred p;\n\t"
                    "mbarrier.try_wait.parity.shared.b64 p, [%1], %2;\n\t"
                    "selp.b32 %0, 1, 0, p;\n\t}"
                    : "=r"(done) : "r"(mbw), "r"(ph) : "memory");
                while (!done) {
                    asm volatile(
                        "{\n\t.reg .pred p;\n\t"
                        "mbarrier.try_wait.parity.shared.b64 p, [%1], %2, 0x989680;\n\t"
                        "selp.b32 %0, 1, 0, p;\n\t}"
                        : "=r"(done) : "r"(mbw), "r"(ph) : "memory");
                }
            }

            const float* tl = tile[t & 3];
            int e0 = (t0 + t) * ET;
            for (int h = hb; h < total; h += 128) {
                int packed = list[h];
                int tk = packed >> 8;
                int vl = packed & 255;
                int s  = tk & (S - 1);
                float4 p = __ldg(reinterpret_cast<const float4*>(
                    W_p + (size_t)s * E + e0) + j);
                float4 r;
                r.x = tl[(4 * j + 0) * SSTRIDE + vl] + p.x;
                r.y = tl[(4 * j + 1) * SSTRIDE + vl] + p.y;
                r.z = tl[(4 * j + 2) * SSTRIDE + vl] + p.z;
                r.w = tl[(4 * j + 3) * SSTRIDE + vl] + p.w;
                __stcs(reinterpret_cast<float4*>(out + (size_t)tk * E + e0) + j, r);
            }
            __syncthreads();   // buffer t fully drained before its reissue
        }
    } else {
        // ---- Fallback (pathological token skew; never hit by this input).
        __syncthreads();
        for (int t = 0; t < nt; t++) {
            int row0 = (t0 + t) * ET;
#pragma unroll
            for (int i = 0; i < 2; i++) {
                int idx = tid + 256 * i;
                int r = idx >> 6, c = idx & 63;
                float4 val = __ldg(reinterpret_cast<const float4*>(
                    W_e + (size_t)(row0 + r) * V + v0) + c);
                *reinterpret_cast<float4*>(&tile[3][r * SSTRIDE + 4 * c]) = val;
            }
            __syncthreads();
            for (int idx = tid; idx < NTOK; idx += 256) {
                int v = __ldg(&tokens[idx]);
                if ((v >> 8) == bin) {
                    int vl = v & 255;
                    int s  = idx & (S - 1);
                    for (int rr = 0; rr < ET; rr++)
                        out[(size_t)idx * E + row0 + rr] =
                            tile[3][rr * SSTRIDE + vl] + W_p[(size_t)s * E + row0 + rr];
                }
            }
            __syncthreads();
        }
    }
}

extern "C" void kernel_launch(void* const* d_in, const int* in_sizes, int n_in,
                              void* d_out, int out_size) {
    const int*   tokens = (const int*)d_in[0];
    const float* W_e    = (const float*)d_in[1];
    const float* W_p    = (const float*)d_in[2];
    float*       out    = (float*)d_out;

    embed_kernel<<<NBINS * KPB, 256>>>(tokens, W_e, W_p, out);
}